// round 1
// baseline (speedup 1.0000x reference)
#include <cuda_runtime.h>
#include <math.h>

// Problem constants
#define BB 2
#define SS 2048
#define HH 12
#define DHD 64
#define DD 768
#define DFF 3072
#define MM (BB*SS)            // 4096
#define Y_ELEMS ((size_t)BB*SS*DD)          // 3,145,728
#define P_ELEMS ((size_t)BB*HH*SS*SS)       // 100,663,296

// ---------------- scratch (device globals; no allocation allowed) ----------
__device__ float g_q [BB*HH*SS*DHD];   // (b,h,s,dh)
__device__ float g_k [BB*HH*SS*DHD];
__device__ float g_v [BB*HH*SS*DHD];
__device__ float g_av[BB*SS*DD];       // attn_v (b,s,d)
__device__ float g_ao[BB*SS*DD];       // attn_out
__device__ float g_h [BB*SS*DD];       // LN1 out
__device__ float g_f1[BB*SS*DFF];      // gelu(h@W1^T+b1)
__device__ float g_f2[BB*SS*DD];       // f1@W2^T+b2

// ---------------- generic NT GEMM: C[m,n] = sum_k A[m,k]*B[n,k] -----------
// mode: 0 = plain, 1 = +bias, 2 = +bias then exact GELU, 3 = head-permuted out
__global__ void gemm_nt(const float* __restrict__ A, const float* __restrict__ B,
                        const float* __restrict__ bias, float* __restrict__ C,
                        int M, int N, int K, int mode)
{
    __shared__ float As[64][17];
    __shared__ float Bs[64][17];
    const int tid = threadIdx.x;          // 256 threads
    const int tx  = tid & 15;             // n direction
    const int ty  = tid >> 4;             // m direction
    const int m0  = blockIdx.y * 64;
    const int n0  = blockIdx.x * 64;
    const int lk  = tid & 15;
    const int lr  = tid >> 4;

    float acc[4][4] = {};

    for (int k0 = 0; k0 < K; k0 += 16) {
        #pragma unroll
        for (int i = 0; i < 4; i++) {
            int r = lr + i * 16;
            As[r][lk] = A[(size_t)(m0 + r) * K + k0 + lk];
            Bs[r][lk] = B[(size_t)(n0 + r) * K + k0 + lk];
        }
        __syncthreads();
        #pragma unroll
        for (int kk = 0; kk < 16; kk++) {
            float a[4], bv[4];
            #pragma unroll
            for (int i = 0; i < 4; i++) a[i]  = As[ty * 4 + i][kk];
            #pragma unroll
            for (int j = 0; j < 4; j++) bv[j] = Bs[tx * 4 + j][kk];
            #pragma unroll
            for (int i = 0; i < 4; i++)
                #pragma unroll
                for (int j = 0; j < 4; j++)
                    acc[i][j] += a[i] * bv[j];
        }
        __syncthreads();
    }

    #pragma unroll
    for (int i = 0; i < 4; i++) {
        int m = m0 + ty * 4 + i;
        #pragma unroll
        for (int j = 0; j < 4; j++) {
            int n = n0 + tx * 4 + j;
            float v = acc[i][j];
            if (mode == 1 || mode == 2) v += bias[n];
            if (mode == 2) v = 0.5f * v * (1.0f + erff(v * 0.70710678118654752f));
            if (mode == 3) {
                // (m,n) -> q/k/v[(b*H+h)][s][dh]
                int b  = m >> 11;            // m / 2048
                int s  = m & 2047;
                int h  = n >> 6;
                int dh = n & 63;
                C[(((size_t)(b * HH + h)) * SS + s) * DHD + dh] = v;
            } else {
                C[(size_t)m * N + n] = v;
            }
        }
    }
}

// ---------------- fused scores + causal mask + softmax --------------------
// One block (128 thr) per (bh, q). Writes full probability row (incl. zeros).
__global__ void attn_softmax(const float* __restrict__ Q, const float* __restrict__ Kv,
                             float* __restrict__ P)
{
    const int qi = blockIdx.x;
    const int bh = blockIdx.y;
    const int tid = threadIdx.x;   // 128

    const float* qrow = Q + ((size_t)bh * SS + qi) * DHD;
    const float* Kb   = Kv + (size_t)bh * SS * DHD;
    float* Prow       = P + ((size_t)bh * SS + qi) * SS;

    __shared__ float sc[SS];
    __shared__ float qs[DHD];
    __shared__ float redA[4];
    __shared__ float redB[4];

    if (tid < DHD) qs[tid] = qrow[tid];
    __syncthreads();

    const float4* q4 = (const float4*)qs;
    float lmax = -1e30f;
    for (int j = tid; j < SS; j += 128) {
        float s;
        if (j > qi) {
            s = -1e9f;                      // causal mask, matches reference
        } else {
            const float4* k4 = (const float4*)(Kb + (size_t)j * DHD);
            float acc = 0.f;
            #pragma unroll
            for (int t = 0; t < 16; t++) {
                float4 kv = k4[t], qv = q4[t];
                acc += qv.x * kv.x + qv.y * kv.y + qv.z * kv.z + qv.w * kv.w;
            }
            s = acc * 0.125f;               // 1/sqrt(64)
        }
        sc[j] = s;
        lmax = fmaxf(lmax, s);
    }
    // block max
    #pragma unroll
    for (int o = 16; o; o >>= 1) lmax = fmaxf(lmax, __shfl_xor_sync(0xffffffffu, lmax, o));
    if ((tid & 31) == 0) redA[tid >> 5] = lmax;
    __syncthreads();
    const float mx = fmaxf(fmaxf(redA[0], redA[1]), fmaxf(redA[2], redA[3]));

    float lsum = 0.f;
    for (int j = tid; j < SS; j += 128) {
        float e = expf(sc[j] - mx);
        sc[j] = e;
        lsum += e;
    }
    #pragma unroll
    for (int o = 16; o; o >>= 1) lsum += __shfl_xor_sync(0xffffffffu, lsum, o);
    if ((tid & 31) == 0) redB[tid >> 5] = lsum;
    __syncthreads();
    const float inv = 1.0f / (redB[0] + redB[1] + redB[2] + redB[3]);

    for (int j = tid; j < SS; j += 128)
        Prow[j] = sc[j] * inv;
}

// ---------------- batched P@V : AV[b,s, h*64+n] = sum_k P[bh,s,k]*V[bh,k,n] -
__global__ void gemm_pv(const float* __restrict__ P, const float* __restrict__ V,
                        float* __restrict__ AV)
{
    const int bh = blockIdx.y;
    const int m0 = blockIdx.x * 64;
    const float* Pb = P + (size_t)bh * SS * SS;
    const float* Vb = V + (size_t)bh * SS * DHD;

    __shared__ float Ps[64][17];
    __shared__ float Vs[16][65];
    const int tid = threadIdx.x;    // 256
    const int tx = tid & 15;
    const int ty = tid >> 4;
    const int lk = tid & 15;
    const int lr = tid >> 4;
    const int lc = tid & 63;
    const int lr2 = tid >> 6;       // 0..3

    float acc[4][4] = {};

    for (int k0 = 0; k0 < SS; k0 += 16) {
        #pragma unroll
        for (int i = 0; i < 4; i++) {
            int r = lr + i * 16;
            Ps[r][lk] = Pb[(size_t)(m0 + r) * SS + k0 + lk];
        }
        #pragma unroll
        for (int i = 0; i < 4; i++) {
            int r = lr2 + i * 4;
            Vs[r][lc] = Vb[(size_t)(k0 + r) * DHD + lc];
        }
        __syncthreads();
        #pragma unroll
        for (int kk = 0; kk < 16; kk++) {
            float a[4], bv[4];
            #pragma unroll
            for (int i = 0; i < 4; i++) a[i]  = Ps[ty * 4 + i][kk];
            #pragma unroll
            for (int j = 0; j < 4; j++) bv[j] = Vs[kk][tx * 4 + j];
            #pragma unroll
            for (int i = 0; i < 4; i++)
                #pragma unroll
                for (int j = 0; j < 4; j++)
                    acc[i][j] += a[i] * bv[j];
        }
        __syncthreads();
    }

    const int b = bh / HH, h = bh % HH;
    #pragma unroll
    for (int i = 0; i < 4; i++) {
        int s = m0 + ty * 4 + i;
        #pragma unroll
        for (int j = 0; j < 4; j++) {
            int n = tx * 4 + j;
            AV[((size_t)b * SS + s) * DD + h * DHD + n] = acc[i][j];
        }
    }
}

// ---------------- fused residual add + LayerNorm --------------------------
__global__ void add_ln(const float* __restrict__ A, const float* __restrict__ Bv,
                       const float* __restrict__ gamma, const float* __restrict__ beta,
                       float* __restrict__ out)
{
    const int row = blockIdx.x;
    const int tid = threadIdx.x;   // 256
    __shared__ float buf[DD];
    __shared__ float red[8];

    const float* a  = A  + (size_t)row * DD;
    const float* bp = Bv + (size_t)row * DD;

    float lsum = 0.f;
    #pragma unroll
    for (int i = 0; i < 3; i++) {
        int c = tid + i * 256;
        float v = a[c] + bp[c];
        buf[c] = v;
        lsum += v;
    }
    #pragma unroll
    for (int o = 16; o; o >>= 1) lsum += __shfl_xor_sync(0xffffffffu, lsum, o);
    if ((tid & 31) == 0) red[tid >> 5] = lsum;
    __syncthreads();
    float mu = (red[0] + red[1] + red[2] + red[3] + red[4] + red[5] + red[6] + red[7]) * (1.0f / DD);

    float lvar = 0.f;
    #pragma unroll
    for (int i = 0; i < 3; i++) {
        int c = tid + i * 256;
        float d = buf[c] - mu;
        lvar += d * d;
    }
    #pragma unroll
    for (int o = 16; o; o >>= 1) lvar += __shfl_xor_sync(0xffffffffu, lvar, o);
    __syncthreads();
    if ((tid & 31) == 0) red[tid >> 5] = lvar;
    __syncthreads();
    float var = (red[0] + red[1] + red[2] + red[3] + red[4] + red[5] + red[6] + red[7]) * (1.0f / DD);
    float inv = rsqrtf(var + 1e-5f);

    float* o = out + (size_t)row * DD;
    #pragma unroll
    for (int i = 0; i < 3; i++) {
        int c = tid + i * 256;
        o[c] = (buf[c] - mu) * inv * gamma[c] + beta[c];
    }
}

// ---------------------------------------------------------------------------
extern "C" void kernel_launch(void* const* d_in, const int* in_sizes, int n_in,
                              void* d_out, int out_size)
{
    // metadata order: x, attn_mask, Wq, Wk, Wv, Wo, bo, g1, b1, W1, bb1, W2, bb2, g2, b2
    const float* x   = (const float*)d_in[0];
    const float* Wq  = (const float*)d_in[2];
    const float* Wk  = (const float*)d_in[3];
    const float* Wv  = (const float*)d_in[4];
    const float* Wo  = (const float*)d_in[5];
    const float* bo  = (const float*)d_in[6];
    const float* g1  = (const float*)d_in[7];
    const float* b1  = (const float*)d_in[8];
    const float* W1  = (const float*)d_in[9];
    const float* bb1 = (const float*)d_in[10];
    const float* W2  = (const float*)d_in[11];
    const float* bb2 = (const float*)d_in[12];
    const float* g2  = (const float*)d_in[13];
    const float* b2  = (const float*)d_in[14];

    float* y = (float*)d_out;          // first output: y (B,S,D)
    float* P = y + Y_ELEMS;            // second output: attn_p (B,H,S,S)

    float *qp, *kp, *vp, *avp, *aop, *hp, *f1p, *f2p;
    cudaGetSymbolAddress((void**)&qp,  g_q);
    cudaGetSymbolAddress((void**)&kp,  g_k);
    cudaGetSymbolAddress((void**)&vp,  g_v);
    cudaGetSymbolAddress((void**)&avp, g_av);
    cudaGetSymbolAddress((void**)&aop, g_ao);
    cudaGetSymbolAddress((void**)&hp,  g_h);
    cudaGetSymbolAddress((void**)&f1p, g_f1);
    cudaGetSymbolAddress((void**)&f2p, g_f2);

    dim3 g768(DD / 64, MM / 64);       // (12, 64)
    dim3 g3072(DFF / 64, MM / 64);     // (48, 64)

    // QKV projections with head-split layout
    gemm_nt<<<g768, 256>>>(x, Wq, nullptr, qp, MM, DD, DD, 3);
    gemm_nt<<<g768, 256>>>(x, Wk, nullptr, kp, MM, DD, DD, 3);
    gemm_nt<<<g768, 256>>>(x, Wv, nullptr, vp, MM, DD, DD, 3);

    // scores + mask + softmax -> attn_p (directly to output region)
    attn_softmax<<<dim3(SS, BB * HH), 128>>>(qp, kp, P);

    // attn_v = P @ V  (batched over b,h), merged back to (b,s,d)
    gemm_pv<<<dim3(SS / 64, BB * HH), 256>>>(P, vp, avp);

    // output projection + bias
    gemm_nt<<<g768, 256>>>(avp, Wo, bo, aop, MM, DD, DD, 1);

    // h = LN(x + attn_out)
    add_ln<<<MM, 256>>>(x, aop, g1, b1, hp);

    // FFN
    gemm_nt<<<g3072, 256>>>(hp, W1, bb1, f1p, MM, DFF, DD, 2);   // bias + exact GELU
    gemm_nt<<<g768, 256>>>(f1p, W2, bb2, f2p, MM, DD, DFF, 1);   // bias

    // y = LN(h + f)
    add_ln<<<MM, 256>>>(hp, f2p, g2, b2, y);
}

// round 2
// speedup vs baseline: 1.3631x; 1.3631x over previous
#include <cuda_runtime.h>
#include <math.h>
#include <mma.h>

using namespace nvcuda;

// Problem constants
#define BB 2
#define SS 2048
#define HH 12
#define DHD 64
#define DD 768
#define DFF 3072
#define MM (BB*SS)            // 4096
#define Y_ELEMS ((size_t)BB*SS*DD)          // 3,145,728

// ---------------- scratch (device globals; no allocation allowed) ----------
__device__ float g_q [BB*HH*SS*DHD];   // (b,h,s,dh)
__device__ float g_k [BB*HH*SS*DHD];
__device__ float g_v [BB*HH*SS*DHD];
__device__ float g_av[BB*SS*DD];       // attn_v (b,s,d)
__device__ float g_ao[BB*SS*DD];       // attn_out (pre-bias)
__device__ float g_h [BB*SS*DD];       // LN1 out
__device__ float g_f1[BB*SS*DFF];      // h@W1^T (then bias+gelu in place)
__device__ float g_f2[BB*SS*DD];       // f1@W2^T (pre-bias)

// =====================  tf32 tensor-core NT GEMM  ==========================
// C[m,n] = sum_k A[m,k] * B[n,k]
// mode 0: C row-major [M,N].  mode 3: head-split C[((b*H+h)*S+s)*64+dh]
__global__ void __launch_bounds__(256)
gemm_tc_nt(const float* __restrict__ A, const float* __restrict__ B,
           float* __restrict__ C, int M, int N, int K, int mode)
{
    __shared__ float As[128][36];
    __shared__ float Bs[128][36];

    const int tid  = threadIdx.x;
    const int warp = tid >> 5;
    const int wm   = warp & 1;        // 2 warps in m (64 rows each)
    const int wn   = warp >> 1;       // 4 warps in n (32 cols each)
    const int m0   = blockIdx.y * 128;
    const int n0   = blockIdx.x * 128;

    const int lr  = tid >> 3;          // 0..31
    const int lc4 = (tid & 7) * 4;     // 0..28

    wmma::fragment<wmma::accumulator, 16, 16, 8, float> c[4][2];
    #pragma unroll
    for (int i = 0; i < 4; i++)
        #pragma unroll
        for (int j = 0; j < 2; j++)
            wmma::fill_fragment(c[i][j], 0.0f);

    for (int k0 = 0; k0 < K; k0 += 32) {
        #pragma unroll
        for (int i = 0; i < 4; i++) {
            int row = lr + i * 32;
            *(float4*)&As[row][lc4] = *(const float4*)&A[(size_t)(m0 + row) * K + k0 + lc4];
            *(float4*)&Bs[row][lc4] = *(const float4*)&B[(size_t)(n0 + row) * K + k0 + lc4];
        }
        __syncthreads();

        #pragma unroll
        for (int kk = 0; kk < 32; kk += 8) {
            wmma::fragment<wmma::matrix_a, 16, 16, 8, wmma::precision::tf32, wmma::row_major> a[4];
            wmma::fragment<wmma::matrix_b, 16, 16, 8, wmma::precision::tf32, wmma::col_major> b[2];
            #pragma unroll
            for (int i = 0; i < 4; i++) {
                wmma::load_matrix_sync(a[i], &As[wm * 64 + i * 16][kk], 36);
                #pragma unroll
                for (int t = 0; t < a[i].num_elements; t++)
                    a[i].x[t] = wmma::__float_to_tf32(a[i].x[t]);
            }
            #pragma unroll
            for (int j = 0; j < 2; j++) {
                wmma::load_matrix_sync(b[j], &Bs[wn * 32 + j * 16][kk], 36);
                #pragma unroll
                for (int t = 0; t < b[j].num_elements; t++)
                    b[j].x[t] = wmma::__float_to_tf32(b[j].x[t]);
            }
            #pragma unroll
            for (int i = 0; i < 4; i++)
                #pragma unroll
                for (int j = 0; j < 2; j++)
                    wmma::mma_sync(c[i][j], a[i], b[j], c[i][j]);
        }
        __syncthreads();
    }

    #pragma unroll
    for (int i = 0; i < 4; i++) {
        int m = m0 + wm * 64 + i * 16;
        #pragma unroll
        for (int j = 0; j < 2; j++) {
            int n = n0 + wn * 32 + j * 16;
            if (mode == 3) {
                int bidx = m >> 11, s = m & 2047;
                int h = n >> 6, dh = n & 63;
                float* dst = C + (((size_t)(bidx * HH + h)) * SS + s) * DHD + dh;
                wmma::store_matrix_sync(dst, c[i][j], DHD, wmma::mem_row_major);
            } else {
                wmma::store_matrix_sync(C + (size_t)m * N + n, c[i][j], N, wmma::mem_row_major);
            }
        }
    }
}

// =================  tf32 tensor-core P@V (batched, causal)  ================
// AV[b,s, h*64+n] = sum_k P[bh,s,k] * V[bh,k,n]
__global__ void __launch_bounds__(256)
gemm_pv_tc(const float* __restrict__ P, const float* __restrict__ V,
           float* __restrict__ AV)
{
    __shared__ float Ps[128][36];
    __shared__ float Vs[32][68];

    const int bh = blockIdx.y;
    const int m0 = blockIdx.x * 128;
    const float* Pb = P + (size_t)bh * SS * SS;
    const float* Vb = V + (size_t)bh * SS * DHD;

    const int tid  = threadIdx.x;
    const int warp = tid >> 5;
    const int wm   = warp & 3;       // 4 warps in m (32 rows each)
    const int wn   = warp >> 2;      // 2 warps in n (32 cols each)

    const int lr  = tid >> 3;         // 0..31
    const int lc4 = (tid & 7) * 4;
    const int vr  = tid >> 4;         // 0..15
    const int vc4 = (tid & 15) * 4;   // 0..60

    wmma::fragment<wmma::accumulator, 16, 16, 8, float> c[2][2];
    #pragma unroll
    for (int i = 0; i < 2; i++)
        #pragma unroll
        for (int j = 0; j < 2; j++)
            wmma::fill_fragment(c[i][j], 0.0f);

    const int kmax = m0 + 128;        // causal: P[s][k]==0 for k>s

    for (int k0 = 0; k0 < kmax; k0 += 32) {
        #pragma unroll
        for (int i = 0; i < 4; i++) {
            int row = lr + i * 32;
            *(float4*)&Ps[row][lc4] = *(const float4*)&Pb[(size_t)(m0 + row) * SS + k0 + lc4];
        }
        #pragma unroll
        for (int i = 0; i < 2; i++) {
            int row = vr + i * 16;
            *(float4*)&Vs[row][vc4] = *(const float4*)&Vb[(size_t)(k0 + row) * DHD + vc4];
        }
        __syncthreads();

        #pragma unroll
        for (int kk = 0; kk < 32; kk += 8) {
            wmma::fragment<wmma::matrix_a, 16, 16, 8, wmma::precision::tf32, wmma::row_major> a[2];
            wmma::fragment<wmma::matrix_b, 16, 16, 8, wmma::precision::tf32, wmma::row_major> b[2];
            #pragma unroll
            for (int i = 0; i < 2; i++) {
                wmma::load_matrix_sync(a[i], &Ps[wm * 32 + i * 16][kk], 36);
                #pragma unroll
                for (int t = 0; t < a[i].num_elements; t++)
                    a[i].x[t] = wmma::__float_to_tf32(a[i].x[t]);
            }
            #pragma unroll
            for (int j = 0; j < 2; j++) {
                wmma::load_matrix_sync(b[j], &Vs[kk][wn * 32 + j * 16], 68);
                #pragma unroll
                for (int t = 0; t < b[j].num_elements; t++)
                    b[j].x[t] = wmma::__float_to_tf32(b[j].x[t]);
            }
            #pragma unroll
            for (int i = 0; i < 2; i++)
                #pragma unroll
                for (int j = 0; j < 2; j++)
                    wmma::mma_sync(c[i][j], a[i], b[j], c[i][j]);
        }
        __syncthreads();
    }

    const int b = bh / HH, h = bh % HH;
    #pragma unroll
    for (int i = 0; i < 2; i++) {
        int s = m0 + wm * 32 + i * 16;
        #pragma unroll
        for (int j = 0; j < 2; j++) {
            int n = wn * 32 + j * 16;
            float* dst = AV + ((size_t)b * SS + s) * DD + h * DHD + n;
            wmma::store_matrix_sync(dst, c[i][j], DD, wmma::mem_row_major);
        }
    }
}

// ---------------- fused scores + causal mask + softmax --------------------
__global__ void attn_softmax(const float* __restrict__ Q, const float* __restrict__ Kv,
                             float* __restrict__ P)
{
    const int qi = blockIdx.x;
    const int bh = blockIdx.y;
    const int tid = threadIdx.x;   // 128

    const float* qrow = Q + ((size_t)bh * SS + qi) * DHD;
    const float* Kb   = Kv + (size_t)bh * SS * DHD;
    float* Prow       = P + ((size_t)bh * SS + qi) * SS;

    __shared__ float sc[SS];
    __shared__ float qs[DHD];
    __shared__ float redA[4];
    __shared__ float redB[4];

    if (tid < DHD) qs[tid] = qrow[tid];
    __syncthreads();

    const float4* q4 = (const float4*)qs;
    float lmax = -1e30f;
    for (int j = tid; j < SS; j += 128) {
        float s;
        if (j > qi) {
            s = -1e9f;
        } else {
            const float4* k4 = (const float4*)(Kb + (size_t)j * DHD);
            float acc = 0.f;
            #pragma unroll
            for (int t = 0; t < 16; t++) {
                float4 kv = k4[t], qv = q4[t];
                acc += qv.x * kv.x + qv.y * kv.y + qv.z * kv.z + qv.w * kv.w;
            }
            s = acc * 0.125f;
        }
        sc[j] = s;
        lmax = fmaxf(lmax, s);
    }
    #pragma unroll
    for (int o = 16; o; o >>= 1) lmax = fmaxf(lmax, __shfl_xor_sync(0xffffffffu, lmax, o));
    if ((tid & 31) == 0) redA[tid >> 5] = lmax;
    __syncthreads();
    const float mx = fmaxf(fmaxf(redA[0], redA[1]), fmaxf(redA[2], redA[3]));

    float lsum = 0.f;
    for (int j = tid; j < SS; j += 128) {
        float e = expf(sc[j] - mx);
        sc[j] = e;
        lsum += e;
    }
    #pragma unroll
    for (int o = 16; o; o >>= 1) lsum += __shfl_xor_sync(0xffffffffu, lsum, o);
    if ((tid & 31) == 0) redB[tid >> 5] = lsum;
    __syncthreads();
    const float inv = 1.0f / (redB[0] + redB[1] + redB[2] + redB[3]);

    for (int j = tid; j < SS; j += 128)
        Prow[j] = sc[j] * inv;
}

// ---------------- bias + exact GELU (in place on f1) ----------------------
__global__ void bias_gelu(float* __restrict__ F, const float* __restrict__ bias)
{
    const int idx4 = blockIdx.x * 256 + threadIdx.x;
    const size_t base = (size_t)idx4 * 4;
    float4 v = *(float4*)&F[base];
    const int col = (int)(base % DFF);
    float4 bb = *(const float4*)&bias[col];
    v.x += bb.x; v.y += bb.y; v.z += bb.z; v.w += bb.w;
    v.x = 0.5f * v.x * (1.0f + erff(v.x * 0.70710678118654752f));
    v.y = 0.5f * v.y * (1.0f + erff(v.y * 0.70710678118654752f));
    v.z = 0.5f * v.z * (1.0f + erff(v.z * 0.70710678118654752f));
    v.w = 0.5f * v.w * (1.0f + erff(v.w * 0.70710678118654752f));
    *(float4*)&F[base] = v;
}

// ---------------- fused residual add (+optional bias on B) + LayerNorm ----
__global__ void add_ln(const float* __restrict__ A, const float* __restrict__ Bv,
                       const float* __restrict__ bias,
                       const float* __restrict__ gamma, const float* __restrict__ beta,
                       float* __restrict__ out)
{
    const int row = blockIdx.x;
    const int tid = threadIdx.x;   // 256
    __shared__ float buf[DD];
    __shared__ float red[8];

    const float* a  = A  + (size_t)row * DD;
    const float* bp = Bv + (size_t)row * DD;

    float lsum = 0.f;
    #pragma unroll
    for (int i = 0; i < 3; i++) {
        int c = tid + i * 256;
        float v = a[c] + bp[c] + (bias ? bias[c] : 0.0f);
        buf[c] = v;
        lsum += v;
    }
    #pragma unroll
    for (int o = 16; o; o >>= 1) lsum += __shfl_xor_sync(0xffffffffu, lsum, o);
    if ((tid & 31) == 0) red[tid >> 5] = lsum;
    __syncthreads();
    float mu = (red[0]+red[1]+red[2]+red[3]+red[4]+red[5]+red[6]+red[7]) * (1.0f / DD);

    float lvar = 0.f;
    #pragma unroll
    for (int i = 0; i < 3; i++) {
        int c = tid + i * 256;
        float d = buf[c] - mu;
        lvar += d * d;
    }
    #pragma unroll
    for (int o = 16; o; o >>= 1) lvar += __shfl_xor_sync(0xffffffffu, lvar, o);
    __syncthreads();
    if ((tid & 31) == 0) red[tid >> 5] = lvar;
    __syncthreads();
    float var = (red[0]+red[1]+red[2]+red[3]+red[4]+red[5]+red[6]+red[7]) * (1.0f / DD);
    float inv = rsqrtf(var + 1e-5f);

    float* o = out + (size_t)row * DD;
    #pragma unroll
    for (int i = 0; i < 3; i++) {
        int c = tid + i * 256;
        o[c] = (buf[c] - mu) * inv * gamma[c] + beta[c];
    }
}

// ---------------------------------------------------------------------------
extern "C" void kernel_launch(void* const* d_in, const int* in_sizes, int n_in,
                              void* d_out, int out_size)
{
    const float* x   = (const float*)d_in[0];
    const float* Wq  = (const float*)d_in[2];
    const float* Wk  = (const float*)d_in[3];
    const float* Wv  = (const float*)d_in[4];
    const float* Wo  = (const float*)d_in[5];
    const float* bo  = (const float*)d_in[6];
    const float* g1  = (const float*)d_in[7];
    const float* b1  = (const float*)d_in[8];
    const float* W1  = (const float*)d_in[9];
    const float* bb1 = (const float*)d_in[10];
    const float* W2  = (const float*)d_in[11];
    const float* bb2 = (const float*)d_in[12];
    const float* g2  = (const float*)d_in[13];
    const float* b2  = (const float*)d_in[14];

    float* y = (float*)d_out;          // y (B,S,D)
    float* P = y + Y_ELEMS;            // attn_p (B,H,S,S)

    float *qp, *kp, *vp, *avp, *aop, *hp, *f1p, *f2p;
    cudaGetSymbolAddress((void**)&qp,  g_q);
    cudaGetSymbolAddress((void**)&kp,  g_k);
    cudaGetSymbolAddress((void**)&vp,  g_v);
    cudaGetSymbolAddress((void**)&avp, g_av);
    cudaGetSymbolAddress((void**)&aop, g_ao);
    cudaGetSymbolAddress((void**)&hp,  g_h);
    cudaGetSymbolAddress((void**)&f1p, g_f1);
    cudaGetSymbolAddress((void**)&f2p, g_f2);

    dim3 g768 (DD  / 128, MM / 128);   // (6, 32)
    dim3 g3072(DFF / 128, MM / 128);   // (24, 32)

    // QKV projections (tensor core, head-split output)
    gemm_tc_nt<<<g768, 256>>>(x, Wq, qp, MM, DD, DD, 3);
    gemm_tc_nt<<<g768, 256>>>(x, Wk, kp, MM, DD, DD, 3);
    gemm_tc_nt<<<g768, 256>>>(x, Wv, vp, MM, DD, DD, 3);

    // scores + mask + softmax (fp32, writes attn_p directly)
    attn_softmax<<<dim3(SS, BB * HH), 128>>>(qp, kp, P);

    // attn_v = P @ V  (tensor core, causal-truncated k loop)
    gemm_pv_tc<<<dim3(SS / 128, BB * HH), 256>>>(P, vp, avp);

    // output projection (bias folded into add_ln)
    gemm_tc_nt<<<g768, 256>>>(avp, Wo, aop, MM, DD, DD, 0);

    // h = LN(x + attn_out + bo)
    add_ln<<<MM, 256>>>(x, aop, bo, g1, b1, hp);

    // FFN
    gemm_tc_nt<<<g3072, 256>>>(hp, W1, f1p, MM, DFF, DD, 0);
    bias_gelu<<<(int)((size_t)MM * DFF / 4 / 256), 256>>>(f1p, bb1);
    gemm_tc_nt<<<g768, 256>>>(f1p, W2, f2p, MM, DD, DFF, 0);

    // y = LN(h + f + bb2)
    add_ln<<<MM, 256>>>(hp, f2p, bb2, g2, b2, y);
}

// round 3
// speedup vs baseline: 2.8994x; 2.1271x over previous
#include <cuda_runtime.h>
#include <math.h>
#include <mma.h>

using namespace nvcuda;

// Problem constants
#define BB 2
#define SS 2048
#define HH 12
#define DHD 64
#define DD 768
#define DFF 3072
#define MM (BB*SS)            // 4096
#define Y_ELEMS ((size_t)BB*SS*DD)

// ---------------- scratch (device globals) ---------------------------------
__device__ float g_q [BB*HH*SS*DHD];   // (b,h,s,dh)
__device__ float g_k [BB*HH*SS*DHD];
__device__ float g_v [BB*HH*SS*DHD];
__device__ float g_av[BB*SS*DD];
__device__ float g_ao[BB*SS*DD];
__device__ float g_h [BB*SS*DD];
__device__ float g_f1[BB*SS*DFF];
__device__ float g_f2[BB*SS*DD];

// =====================  tf32 tensor-core NT GEMM  ==========================
__global__ void __launch_bounds__(256)
gemm_tc_nt(const float* __restrict__ A, const float* __restrict__ B,
           float* __restrict__ C, int M, int N, int K, int mode)
{
    __shared__ float As[128][36];
    __shared__ float Bs[128][36];

    const int tid  = threadIdx.x;
    const int warp = tid >> 5;
    const int wm   = warp & 1;
    const int wn   = warp >> 1;
    const int m0   = blockIdx.y * 128;
    const int n0   = blockIdx.x * 128;
    const int lr   = tid >> 3;
    const int lc4  = (tid & 7) * 4;

    wmma::fragment<wmma::accumulator, 16, 16, 8, float> c[4][2];
    #pragma unroll
    for (int i = 0; i < 4; i++)
        #pragma unroll
        for (int j = 0; j < 2; j++)
            wmma::fill_fragment(c[i][j], 0.0f);

    for (int k0 = 0; k0 < K; k0 += 32) {
        #pragma unroll
        for (int i = 0; i < 4; i++) {
            int row = lr + i * 32;
            *(float4*)&As[row][lc4] = *(const float4*)&A[(size_t)(m0 + row) * K + k0 + lc4];
            *(float4*)&Bs[row][lc4] = *(const float4*)&B[(size_t)(n0 + row) * K + k0 + lc4];
        }
        __syncthreads();

        #pragma unroll
        for (int kk = 0; kk < 32; kk += 8) {
            wmma::fragment<wmma::matrix_a, 16, 16, 8, wmma::precision::tf32, wmma::row_major> a[4];
            wmma::fragment<wmma::matrix_b, 16, 16, 8, wmma::precision::tf32, wmma::col_major> b[2];
            #pragma unroll
            for (int i = 0; i < 4; i++) {
                wmma::load_matrix_sync(a[i], &As[wm * 64 + i * 16][kk], 36);
                #pragma unroll
                for (int t = 0; t < a[i].num_elements; t++)
                    a[i].x[t] = wmma::__float_to_tf32(a[i].x[t]);
            }
            #pragma unroll
            for (int j = 0; j < 2; j++) {
                wmma::load_matrix_sync(b[j], &Bs[wn * 32 + j * 16][kk], 36);
                #pragma unroll
                for (int t = 0; t < b[j].num_elements; t++)
                    b[j].x[t] = wmma::__float_to_tf32(b[j].x[t]);
            }
            #pragma unroll
            for (int i = 0; i < 4; i++)
                #pragma unroll
                for (int j = 0; j < 2; j++)
                    wmma::mma_sync(c[i][j], a[i], b[j], c[i][j]);
        }
        __syncthreads();
    }

    #pragma unroll
    for (int i = 0; i < 4; i++) {
        int m = m0 + wm * 64 + i * 16;
        #pragma unroll
        for (int j = 0; j < 2; j++) {
            int n = n0 + wn * 32 + j * 16;
            if (mode == 3) {
                int bidx = m >> 11, s = m & 2047;
                int h = n >> 6, dh = n & 63;
                float* dst = C + (((size_t)(bidx * HH + h)) * SS + s) * DHD + dh;
                wmma::store_matrix_sync(dst, c[i][j], DHD, wmma::mem_row_major);
            } else {
                wmma::store_matrix_sync(C + (size_t)m * N + n, c[i][j], N, wmma::mem_row_major);
            }
        }
    }
}

// ==============  fused flash-style attention (tensor core)  ================
// One block per (bh, 128-query tile). Computes S=QK^T/8 (tf32), e=exp(S) with
// causal mask, writes unnormalized e to P, accumulates O += e@V, then
// rescales P rows and O by 1/rowsum. Upper-triangle P tiles are zero-filled.
#define ATT_LDQ 68
#define ATT_LDS 132
#define ATT_SMEM_FLOATS (3*128*ATT_LDQ + 128*ATT_LDS + 128)

__global__ void __launch_bounds__(256, 1)
attn_fused(const float* __restrict__ Q, const float* __restrict__ K,
           const float* __restrict__ V, float* __restrict__ P,
           float* __restrict__ AV)
{
    extern __shared__ float sm[];
    float* Qs = sm;                       // [128][68]
    float* Ks = Qs + 128 * ATT_LDQ;       // [128][68]
    float* Vs = Ks + 128 * ATT_LDQ;       // [128][68]
    float* Ss = Vs + 128 * ATT_LDQ;       // [128][132]
    float* ls = Ss + 128 * ATT_LDS;       // [128]

    const int bh  = blockIdx.y;
    const int qt  = gridDim.x - 1 - blockIdx.x;   // heavy tiles first
    const int m0  = qt * 128;
    const int tid = threadIdx.x;
    const int warp = tid >> 5;
    const int wm = warp & 1;       // 64-row half
    const int wn = warp >> 1;      // 32-col quarter (S) / 16-col quarter (O)

    const float* Qb = Q + ((size_t)bh * SS + m0) * DHD;
    const float* Kb = K + (size_t)bh * SS * DHD;
    const float* Vb = V + (size_t)bh * SS * DHD;
    float* Pb = P + ((size_t)bh * SS + m0) * SS;

    // load Q tile, pre-scaled by 1/sqrt(64)
    for (int i = tid; i < 128 * 16; i += 256) {
        int r = i >> 4, c4 = (i & 15) * 4;
        float4 v = *(const float4*)&Qb[(size_t)r * DHD + c4];
        v.x *= 0.125f; v.y *= 0.125f; v.z *= 0.125f; v.w *= 0.125f;
        *(float4*)&Qs[r * ATT_LDQ + c4] = v;
    }
    if (tid < 128) ls[tid] = 0.0f;

    wmma::fragment<wmma::accumulator, 16, 16, 8, float> co[4];
    #pragma unroll
    for (int i = 0; i < 4; i++) wmma::fill_fragment(co[i], 0.0f);

    __syncthreads();

    for (int kt = 0; kt <= qt; kt++) {
        const int k0 = kt * 128;
        // load K and V tiles
        for (int i = tid; i < 128 * 16; i += 256) {
            int r = i >> 4, c4 = (i & 15) * 4;
            *(float4*)&Ks[r * ATT_LDQ + c4] = *(const float4*)&Kb[(size_t)(k0 + r) * DHD + c4];
            *(float4*)&Vs[r * ATT_LDQ + c4] = *(const float4*)&Vb[(size_t)(k0 + r) * DHD + c4];
        }
        __syncthreads();

        // S = Qs @ Ks^T  (warp tile 64x32)
        wmma::fragment<wmma::accumulator, 16, 16, 8, float> cs[4][2];
        #pragma unroll
        for (int i = 0; i < 4; i++)
            #pragma unroll
            for (int j = 0; j < 2; j++)
                wmma::fill_fragment(cs[i][j], 0.0f);

        #pragma unroll
        for (int kk = 0; kk < 64; kk += 8) {
            wmma::fragment<wmma::matrix_a, 16, 16, 8, wmma::precision::tf32, wmma::row_major> a[4];
            wmma::fragment<wmma::matrix_b, 16, 16, 8, wmma::precision::tf32, wmma::col_major> b[2];
            #pragma unroll
            for (int i = 0; i < 4; i++) {
                wmma::load_matrix_sync(a[i], &Qs[(wm * 64 + i * 16) * ATT_LDQ + kk], ATT_LDQ);
                #pragma unroll
                for (int t = 0; t < a[i].num_elements; t++)
                    a[i].x[t] = wmma::__float_to_tf32(a[i].x[t]);
            }
            #pragma unroll
            for (int j = 0; j < 2; j++) {
                wmma::load_matrix_sync(b[j], &Ks[(wn * 32 + j * 16) * ATT_LDQ + kk], ATT_LDQ);
                #pragma unroll
                for (int t = 0; t < b[j].num_elements; t++)
                    b[j].x[t] = wmma::__float_to_tf32(b[j].x[t]);
            }
            #pragma unroll
            for (int i = 0; i < 4; i++)
                #pragma unroll
                for (int j = 0; j < 2; j++)
                    wmma::mma_sync(cs[i][j], a[i], b[j], cs[i][j]);
        }
        #pragma unroll
        for (int i = 0; i < 4; i++)
            #pragma unroll
            for (int j = 0; j < 2; j++)
                wmma::store_matrix_sync(&Ss[(wm * 64 + i * 16) * ATT_LDS + wn * 32 + j * 16],
                                        cs[i][j], ATT_LDS, wmma::mem_row_major);
        __syncthreads();

        // exp + causal mask + row-sum + write unnormalized e to P
        {
            int r  = tid >> 1;
            int c0 = (tid & 1) * 64;
            int grow = m0 + r;
            float partial = 0.0f;
            #pragma unroll
            for (int c = 0; c < 64; c += 4) {
                int gc = k0 + c0 + c;
                float4 v = *(float4*)&Ss[r * ATT_LDS + c0 + c];
                v.x = (gc + 0 <= grow) ? __expf(v.x) : 0.0f;
                v.y = (gc + 1 <= grow) ? __expf(v.y) : 0.0f;
                v.z = (gc + 2 <= grow) ? __expf(v.z) : 0.0f;
                v.w = (gc + 3 <= grow) ? __expf(v.w) : 0.0f;
                partial += v.x + v.y + v.z + v.w;
                *(float4*)&Ss[r * ATT_LDS + c0 + c] = v;
                *(float4*)&Pb[(size_t)r * SS + gc] = v;
            }
            atomicAdd(&ls[r], partial);
        }
        __syncthreads();

        // O += e @ V  (warp tile 64x16)
        #pragma unroll
        for (int kk = 0; kk < 128; kk += 8) {
            wmma::fragment<wmma::matrix_a, 16, 16, 8, wmma::precision::tf32, wmma::row_major> a[4];
            wmma::fragment<wmma::matrix_b, 16, 16, 8, wmma::precision::tf32, wmma::row_major> b;
            #pragma unroll
            for (int i = 0; i < 4; i++) {
                wmma::load_matrix_sync(a[i], &Ss[(wm * 64 + i * 16) * ATT_LDS + kk], ATT_LDS);
                #pragma unroll
                for (int t = 0; t < a[i].num_elements; t++)
                    a[i].x[t] = wmma::__float_to_tf32(a[i].x[t]);
            }
            wmma::load_matrix_sync(b, &Vs[kk * ATT_LDQ + wn * 16], ATT_LDQ);
            #pragma unroll
            for (int t = 0; t < b.num_elements; t++)
                b.x[t] = wmma::__float_to_tf32(b.x[t]);
            #pragma unroll
            for (int i = 0; i < 4; i++)
                wmma::mma_sync(co[i], a[i], b, co[i]);
        }
        __syncthreads();
    }

    // zero-fill fully masked P region
    const int zc0 = (qt + 1) * 128;
    if (zc0 < SS) {
        const int rl4 = (SS - zc0) >> 2;
        const float4 z4 = make_float4(0.f, 0.f, 0.f, 0.f);
        for (int i = tid; i < 128 * rl4; i += 256) {
            int r = i / rl4, c4 = (i - r * rl4) * 4;
            *(float4*)&Pb[(size_t)r * SS + zc0 + c4] = z4;
        }
    }

    // stage O to smem, divide by rowsum, write AV
    #pragma unroll
    for (int i = 0; i < 4; i++)
        wmma::store_matrix_sync(&Ss[(wm * 64 + i * 16) * ATT_LDQ + wn * 16],
                                co[i], ATT_LDQ, wmma::mem_row_major);
    __syncthreads();

    const int bi = bh / HH, hi = bh % HH;
    {
        int r  = tid >> 1;
        int c0 = (tid & 1) * 32;
        float inv = 1.0f / ls[r];
        float* dst = AV + ((size_t)bi * SS + m0 + r) * DD + hi * DHD + c0;
        #pragma unroll
        for (int c = 0; c < 32; c += 4) {
            float4 v = *(float4*)&Ss[r * ATT_LDQ + c0 + c];
            v.x *= inv; v.y *= inv; v.z *= inv; v.w *= inv;
            *(float4*)&dst[c] = v;
        }
    }

    // rescale the lower-triangle P region by 1/rowsum
    {
        const int rl4 = zc0 >> 2;
        for (int i = tid; i < 128 * rl4; i += 256) {
            int r = i / rl4, c4 = (i - r * rl4) * 4;
            float inv = 1.0f / ls[r];
            float4 v = *(float4*)&Pb[(size_t)r * SS + c4];
            v.x *= inv; v.y *= inv; v.z *= inv; v.w *= inv;
            *(float4*)&Pb[(size_t)r * SS + c4] = v;
        }
    }
}

// ---------------- bias + exact GELU (in place on f1) ----------------------
__global__ void bias_gelu(float* __restrict__ F, const float* __restrict__ bias)
{
    const int idx4 = blockIdx.x * 256 + threadIdx.x;
    const size_t base = (size_t)idx4 * 4;
    float4 v = *(float4*)&F[base];
    const int col = (int)(base % DFF);
    float4 bb = *(const float4*)&bias[col];
    v.x += bb.x; v.y += bb.y; v.z += bb.z; v.w += bb.w;
    v.x = 0.5f * v.x * (1.0f + erff(v.x * 0.70710678118654752f));
    v.y = 0.5f * v.y * (1.0f + erff(v.y * 0.70710678118654752f));
    v.z = 0.5f * v.z * (1.0f + erff(v.z * 0.70710678118654752f));
    v.w = 0.5f * v.w * (1.0f + erff(v.w * 0.70710678118654752f));
    *(float4*)&F[base] = v;
}

// ---------------- fused residual add (+bias) + LayerNorm ------------------
__global__ void add_ln(const float* __restrict__ A, const float* __restrict__ Bv,
                       const float* __restrict__ bias,
                       const float* __restrict__ gamma, const float* __restrict__ beta,
                       float* __restrict__ out)
{
    const int row = blockIdx.x;
    const int tid = threadIdx.x;
    __shared__ float buf[DD];
    __shared__ float red[8];

    const float* a  = A  + (size_t)row * DD;
    const float* bp = Bv + (size_t)row * DD;

    float lsum = 0.f;
    #pragma unroll
    for (int i = 0; i < 3; i++) {
        int c = tid + i * 256;
        float v = a[c] + bp[c] + (bias ? bias[c] : 0.0f);
        buf[c] = v;
        lsum += v;
    }
    #pragma unroll
    for (int o = 16; o; o >>= 1) lsum += __shfl_xor_sync(0xffffffffu, lsum, o);
    if ((tid & 31) == 0) red[tid >> 5] = lsum;
    __syncthreads();
    float mu = (red[0]+red[1]+red[2]+red[3]+red[4]+red[5]+red[6]+red[7]) * (1.0f / DD);

    float lvar = 0.f;
    #pragma unroll
    for (int i = 0; i < 3; i++) {
        int c = tid + i * 256;
        float d = buf[c] - mu;
        lvar += d * d;
    }
    #pragma unroll
    for (int o = 16; o; o >>= 1) lvar += __shfl_xor_sync(0xffffffffu, lvar, o);
    __syncthreads();
    if ((tid & 31) == 0) red[tid >> 5] = lvar;
    __syncthreads();
    float var = (red[0]+red[1]+red[2]+red[3]+red[4]+red[5]+red[6]+red[7]) * (1.0f / DD);
    float inv = rsqrtf(var + 1e-5f);

    float* o = out + (size_t)row * DD;
    #pragma unroll
    for (int i = 0; i < 3; i++) {
        int c = tid + i * 256;
        o[c] = (buf[c] - mu) * inv * gamma[c] + beta[c];
    }
}

// ---------------------------------------------------------------------------
extern "C" void kernel_launch(void* const* d_in, const int* in_sizes, int n_in,
                              void* d_out, int out_size)
{
    const float* x   = (const float*)d_in[0];
    const float* Wq  = (const float*)d_in[2];
    const float* Wk  = (const float*)d_in[3];
    const float* Wv  = (const float*)d_in[4];
    const float* Wo  = (const float*)d_in[5];
    const float* bo  = (const float*)d_in[6];
    const float* g1  = (const float*)d_in[7];
    const float* b1  = (const float*)d_in[8];
    const float* W1  = (const float*)d_in[9];
    const float* bb1 = (const float*)d_in[10];
    const float* W2  = (const float*)d_in[11];
    const float* bb2 = (const float*)d_in[12];
    const float* g2  = (const float*)d_in[13];
    const float* b2  = (const float*)d_in[14];

    float* y = (float*)d_out;
    float* P = y + Y_ELEMS;

    float *qp, *kp, *vp, *avp, *aop, *hp, *f1p, *f2p;
    cudaGetSymbolAddress((void**)&qp,  g_q);
    cudaGetSymbolAddress((void**)&kp,  g_k);
    cudaGetSymbolAddress((void**)&vp,  g_v);
    cudaGetSymbolAddress((void**)&avp, g_av);
    cudaGetSymbolAddress((void**)&aop, g_ao);
    cudaGetSymbolAddress((void**)&hp,  g_h);
    cudaGetSymbolAddress((void**)&f1p, g_f1);
    cudaGetSymbolAddress((void**)&f2p, g_f2);

    dim3 g768 (DD  / 128, MM / 128);
    dim3 g3072(DFF / 128, MM / 128);

    // QKV projections (tensor core, head-split output)
    gemm_tc_nt<<<g768, 256>>>(x, Wq, qp, MM, DD, DD, 3);
    gemm_tc_nt<<<g768, 256>>>(x, Wk, kp, MM, DD, DD, 3);
    gemm_tc_nt<<<g768, 256>>>(x, Wv, vp, MM, DD, DD, 3);

    // fused attention: scores + mask + softmax + P output + P@V
    static const size_t att_smem = (size_t)ATT_SMEM_FLOATS * sizeof(float);
    cudaFuncSetAttribute(attn_fused, cudaFuncAttributeMaxDynamicSharedMemorySize,
                         (int)att_smem);
    attn_fused<<<dim3(SS / 128, BB * HH), 256, att_smem>>>(qp, kp, vp, P, avp);

    // output projection (bias folded into add_ln)
    gemm_tc_nt<<<g768, 256>>>(avp, Wo, aop, MM, DD, DD, 0);

    // h = LN(x + attn_out + bo)
    add_ln<<<MM, 256>>>(x, aop, bo, g1, b1, hp);

    // FFN
    gemm_tc_nt<<<g3072, 256>>>(hp, W1, f1p, MM, DFF, DD, 0);
    bias_gelu<<<(int)((size_t)MM * DFF / 4 / 256), 256>>>(f1p, bb1);
    gemm_tc_nt<<<g768, 256>>>(f1p, W2, f2p, MM, DD, DFF, 0);

    // y = LN(h + f + bb2)
    add_ln<<<MM, 256>>>(hp, f2p, bb2, g2, b2, y);
}

// round 4
// speedup vs baseline: 3.3165x; 1.1439x over previous
#include <cuda_runtime.h>
#include <math.h>
#include <mma.h>

using namespace nvcuda;

// Problem constants
#define BB 2
#define SS 2048
#define HH 12
#define DHD 64
#define DD 768
#define DFF 3072
#define MM (BB*SS)
#define Y_ELEMS ((size_t)BB*SS*DD)

// ---------------- scratch (device globals) ---------------------------------
__device__ float g_q [BB*HH*SS*DHD];
__device__ float g_k [BB*HH*SS*DHD];
__device__ float g_v [BB*HH*SS*DHD];
__device__ float g_av[BB*SS*DD];
__device__ float g_ao[BB*SS*DD];
__device__ float g_h [BB*SS*DD];
__device__ float g_f1[BB*SS*DFF];
__device__ float g_f2[BB*SS*DD];

__device__ __forceinline__ float4 cvt_tf32_4(float4 v) {
    v.x = wmma::__float_to_tf32(v.x);
    v.y = wmma::__float_to_tf32(v.y);
    v.z = wmma::__float_to_tf32(v.z);
    v.w = wmma::__float_to_tf32(v.w);
    return v;
}

// ============  tf32 NT GEMM, double-buffered, cvt-at-store  ================
// C[m,n] = sum_k A[m,k]*B[n,k].  mode 0: row-major C. mode 3: head-split.
#define GLD 36
#define GBUF (128*GLD)
#define GEMM_SMEM_BYTES (4*GBUF*4)   // 2 bufs x (As+Bs)

__global__ void __launch_bounds__(256)
gemm_tc_nt(const float* __restrict__ A, const float* __restrict__ B,
           float* __restrict__ C, int M, int N, int K, int mode)
{
    extern __shared__ float gsm[];
    float* As = gsm;            // [2][128][36]
    float* Bs = gsm + 2*GBUF;   // [2][128][36]

    const int tid  = threadIdx.x;
    const int warp = tid >> 5;
    const int wm   = warp & 1;
    const int wn   = warp >> 1;
    const int m0   = blockIdx.y * 128;
    const int n0   = blockIdx.x * 128;
    const int lr   = tid >> 3;
    const int lc4  = (tid & 7) * 4;

    wmma::fragment<wmma::accumulator, 16, 16, 8, float> c[4][2];
    #pragma unroll
    for (int i = 0; i < 4; i++)
        #pragma unroll
        for (int j = 0; j < 2; j++)
            wmma::fill_fragment(c[i][j], 0.0f);

    const int T = K >> 5;
    float4 pa[4], pb[4];

    // preload tile 0
    #pragma unroll
    for (int i = 0; i < 4; i++) {
        int row = lr + i * 32;
        pa[i] = *(const float4*)&A[(size_t)(m0 + row) * K + lc4];
        pb[i] = *(const float4*)&B[(size_t)(n0 + row) * K + lc4];
    }
    #pragma unroll
    for (int i = 0; i < 4; i++) {
        int row = lr + i * 32;
        *(float4*)&As[row * GLD + lc4] = cvt_tf32_4(pa[i]);
        *(float4*)&Bs[row * GLD + lc4] = cvt_tf32_4(pb[i]);
    }
    __syncthreads();

    for (int t = 0; t < T; t++) {
        const int cur = (t & 1) * GBUF;
        const bool pf = (t + 1 < T);
        if (pf) {
            const int k0 = (t + 1) << 5;
            #pragma unroll
            for (int i = 0; i < 4; i++) {
                int row = lr + i * 32;
                pa[i] = *(const float4*)&A[(size_t)(m0 + row) * K + k0 + lc4];
                pb[i] = *(const float4*)&B[(size_t)(n0 + row) * K + k0 + lc4];
            }
        }

        #pragma unroll
        for (int kk = 0; kk < 32; kk += 8) {
            wmma::fragment<wmma::matrix_a, 16, 16, 8, wmma::precision::tf32, wmma::row_major> a[4];
            wmma::fragment<wmma::matrix_b, 16, 16, 8, wmma::precision::tf32, wmma::col_major> b[2];
            #pragma unroll
            for (int i = 0; i < 4; i++)
                wmma::load_matrix_sync(a[i], &As[cur + (wm * 64 + i * 16) * GLD + kk], GLD);
            #pragma unroll
            for (int j = 0; j < 2; j++)
                wmma::load_matrix_sync(b[j], &Bs[cur + (wn * 32 + j * 16) * GLD + kk], GLD);
            #pragma unroll
            for (int i = 0; i < 4; i++)
                #pragma unroll
                for (int j = 0; j < 2; j++)
                    wmma::mma_sync(c[i][j], a[i], b[j], c[i][j]);
        }

        if (pf) {
            const int nxt = ((t + 1) & 1) * GBUF;
            #pragma unroll
            for (int i = 0; i < 4; i++) {
                int row = lr + i * 32;
                *(float4*)&As[nxt + row * GLD + lc4] = cvt_tf32_4(pa[i]);
                *(float4*)&Bs[nxt + row * GLD + lc4] = cvt_tf32_4(pb[i]);
            }
        }
        __syncthreads();
    }

    #pragma unroll
    for (int i = 0; i < 4; i++) {
        int m = m0 + wm * 64 + i * 16;
        #pragma unroll
        for (int j = 0; j < 2; j++) {
            int n = n0 + wn * 32 + j * 16;
            if (mode == 3) {
                int bidx = m >> 11, s = m & 2047;
                int h = n >> 6, dh = n & 63;
                float* dst = C + (((size_t)(bidx * HH + h)) * SS + s) * DHD + dh;
                wmma::store_matrix_sync(dst, c[i][j], DHD, wmma::mem_row_major);
            } else {
                wmma::store_matrix_sync(C + (size_t)m * N + n, c[i][j], N, wmma::mem_row_major);
            }
        }
    }
}

// ==============  fused flash-style attention (512 threads)  ================
#define ATT_LDQ 68
#define ATT_LDS 132
#define ATT_SMEM_FLOATS (3*128*ATT_LDQ + 128*ATT_LDS + 128)

__global__ void __launch_bounds__(512, 1)
attn_fused(const float* __restrict__ Q, const float* __restrict__ K,
           const float* __restrict__ V, float* __restrict__ P,
           float* __restrict__ AV)
{
    extern __shared__ float sm[];
    float* Qs = sm;                       // [128][68] tf32
    float* Ks = Qs + 128 * ATT_LDQ;       // [128][68] tf32
    float* Vs = Ks + 128 * ATT_LDQ;       // [128][68] tf32
    float* Ss = Vs + 128 * ATT_LDQ;       // [128][132]
    float* ls = Ss + 128 * ATT_LDS;       // [128]

    const int bh  = blockIdx.y;
    const int qt  = gridDim.x - 1 - blockIdx.x;   // heavy tiles first
    const int m0  = qt * 128;
    const int tid = threadIdx.x;
    const int warp = tid >> 5;
    const int wm = warp & 3;       // 32-row group
    const int wn = warp >> 2;      // 32-col (S) / 16-col (O) group

    const float* Qb = Q + ((size_t)bh * SS + m0) * DHD;
    const float* Kb = K + (size_t)bh * SS * DHD;
    const float* Vb = V + (size_t)bh * SS * DHD;
    float* Pb = P + ((size_t)bh * SS + m0) * SS;

    // load Q tile, pre-scaled by 1/8, tf32-rounded
    for (int i = tid; i < 128 * 16; i += 512) {
        int r = i >> 4, c4 = (i & 15) * 4;
        float4 v = *(const float4*)&Qb[(size_t)r * DHD + c4];
        v.x *= 0.125f; v.y *= 0.125f; v.z *= 0.125f; v.w *= 0.125f;
        *(float4*)&Qs[r * ATT_LDQ + c4] = cvt_tf32_4(v);
    }
    if (tid < 128) ls[tid] = 0.0f;

    wmma::fragment<wmma::accumulator, 16, 16, 8, float> co[2];
    #pragma unroll
    for (int i = 0; i < 2; i++) wmma::fill_fragment(co[i], 0.0f);

    __syncthreads();

    for (int kt = 0; kt <= qt; kt++) {
        const int k0 = kt * 128;
        for (int i = tid; i < 128 * 16; i += 512) {
            int r = i >> 4, c4 = (i & 15) * 4;
            *(float4*)&Ks[r * ATT_LDQ + c4] =
                cvt_tf32_4(*(const float4*)&Kb[(size_t)(k0 + r) * DHD + c4]);
            *(float4*)&Vs[r * ATT_LDQ + c4] =
                cvt_tf32_4(*(const float4*)&Vb[(size_t)(k0 + r) * DHD + c4]);
        }
        __syncthreads();

        // S = Qs @ Ks^T  (warp tile 32x32)
        wmma::fragment<wmma::accumulator, 16, 16, 8, float> cs[2][2];
        #pragma unroll
        for (int i = 0; i < 2; i++)
            #pragma unroll
            for (int j = 0; j < 2; j++)
                wmma::fill_fragment(cs[i][j], 0.0f);

        #pragma unroll
        for (int kk = 0; kk < 64; kk += 8) {
            wmma::fragment<wmma::matrix_a, 16, 16, 8, wmma::precision::tf32, wmma::row_major> a[2];
            wmma::fragment<wmma::matrix_b, 16, 16, 8, wmma::precision::tf32, wmma::col_major> b[2];
            #pragma unroll
            for (int i = 0; i < 2; i++)
                wmma::load_matrix_sync(a[i], &Qs[(wm * 32 + i * 16) * ATT_LDQ + kk], ATT_LDQ);
            #pragma unroll
            for (int j = 0; j < 2; j++)
                wmma::load_matrix_sync(b[j], &Ks[(wn * 32 + j * 16) * ATT_LDQ + kk], ATT_LDQ);
            #pragma unroll
            for (int i = 0; i < 2; i++)
                #pragma unroll
                for (int j = 0; j < 2; j++)
                    wmma::mma_sync(cs[i][j], a[i], b[j], cs[i][j]);
        }
        #pragma unroll
        for (int i = 0; i < 2; i++)
            #pragma unroll
            for (int j = 0; j < 2; j++)
                wmma::store_matrix_sync(&Ss[(wm * 32 + i * 16) * ATT_LDS + wn * 32 + j * 16],
                                        cs[i][j], ATT_LDS, wmma::mem_row_major);
        __syncthreads();

        // exp + causal mask + row-sum; fp32 e -> P, tf32 e -> Ss
        {
            int r  = tid >> 2;
            int c0 = (tid & 3) * 32;
            int grow = m0 + r;
            float partial = 0.0f;
            #pragma unroll
            for (int c = 0; c < 32; c += 4) {
                int gc = k0 + c0 + c;
                float4 v = *(float4*)&Ss[r * ATT_LDS + c0 + c];
                v.x = (gc + 0 <= grow) ? __expf(v.x) : 0.0f;
                v.y = (gc + 1 <= grow) ? __expf(v.y) : 0.0f;
                v.z = (gc + 2 <= grow) ? __expf(v.z) : 0.0f;
                v.w = (gc + 3 <= grow) ? __expf(v.w) : 0.0f;
                partial += v.x + v.y + v.z + v.w;
                *(float4*)&Pb[(size_t)r * SS + gc] = v;
                *(float4*)&Ss[r * ATT_LDS + c0 + c] = cvt_tf32_4(v);
            }
            atomicAdd(&ls[r], partial);
        }
        __syncthreads();

        // O += e @ V  (warp tile 32x16)
        #pragma unroll
        for (int kk = 0; kk < 128; kk += 8) {
            wmma::fragment<wmma::matrix_a, 16, 16, 8, wmma::precision::tf32, wmma::row_major> a[2];
            wmma::fragment<wmma::matrix_b, 16, 16, 8, wmma::precision::tf32, wmma::row_major> b;
            #pragma unroll
            for (int i = 0; i < 2; i++)
                wmma::load_matrix_sync(a[i], &Ss[(wm * 32 + i * 16) * ATT_LDS + kk], ATT_LDS);
            wmma::load_matrix_sync(b, &Vs[kk * ATT_LDQ + wn * 16], ATT_LDQ);
            #pragma unroll
            for (int i = 0; i < 2; i++)
                wmma::mma_sync(co[i], a[i], b, co[i]);
        }
        __syncthreads();
    }

    // zero-fill fully masked P region
    const int zc0 = (qt + 1) * 128;
    if (zc0 < SS) {
        const int rl4 = (SS - zc0) >> 2;
        const float4 z4 = make_float4(0.f, 0.f, 0.f, 0.f);
        for (int i = tid; i < 128 * rl4; i += 512) {
            int r = i / rl4, c4 = (i - r * rl4) * 4;
            *(float4*)&Pb[(size_t)r * SS + zc0 + c4] = z4;
        }
    }

    // stage O to smem
    #pragma unroll
    for (int i = 0; i < 2; i++)
        wmma::store_matrix_sync(&Ss[(wm * 32 + i * 16) * ATT_LDQ + wn * 16],
                                co[i], ATT_LDQ, wmma::mem_row_major);
    __syncthreads();

    const int bi = bh / HH, hi = bh % HH;
    {
        int r  = tid >> 2;
        int c0 = (tid & 3) * 16;
        float inv = 1.0f / ls[r];
        float* dst = AV + ((size_t)bi * SS + m0 + r) * DD + hi * DHD + c0;
        #pragma unroll
        for (int c = 0; c < 16; c += 4) {
            float4 v = *(float4*)&Ss[r * ATT_LDQ + c0 + c];
            v.x *= inv; v.y *= inv; v.z *= inv; v.w *= inv;
            *(float4*)&dst[c] = v;
        }
    }

    // rescale lower-triangle P by 1/rowsum
    {
        const int rl4 = zc0 >> 2;
        for (int i = tid; i < 128 * rl4; i += 512) {
            int r = i / rl4, c4 = (i - r * rl4) * 4;
            float inv = 1.0f / ls[r];
            float4 v = *(float4*)&Pb[(size_t)r * SS + c4];
            v.x *= inv; v.y *= inv; v.z *= inv; v.w *= inv;
            *(float4*)&Pb[(size_t)r * SS + c4] = v;
        }
    }
}

// ---------------- bias + exact GELU (in place) -----------------------------
__global__ void bias_gelu(float* __restrict__ F, const float* __restrict__ bias)
{
    const int idx4 = blockIdx.x * 256 + threadIdx.x;
    const size_t base = (size_t)idx4 * 4;
    float4 v = *(float4*)&F[base];
    const int col = (int)(base % DFF);
    float4 bb = *(const float4*)&bias[col];
    v.x += bb.x; v.y += bb.y; v.z += bb.z; v.w += bb.w;
    v.x = 0.5f * v.x * (1.0f + erff(v.x * 0.70710678118654752f));
    v.y = 0.5f * v.y * (1.0f + erff(v.y * 0.70710678118654752f));
    v.z = 0.5f * v.z * (1.0f + erff(v.z * 0.70710678118654752f));
    v.w = 0.5f * v.w * (1.0f + erff(v.w * 0.70710678118654752f));
    *(float4*)&F[base] = v;
}

// ---------------- fused residual add (+bias) + LayerNorm ------------------
__global__ void add_ln(const float* __restrict__ A, const float* __restrict__ Bv,
                       const float* __restrict__ bias,
                       const float* __restrict__ gamma, const float* __restrict__ beta,
                       float* __restrict__ out)
{
    const int row = blockIdx.x;
    const int tid = threadIdx.x;
    __shared__ float buf[DD];
    __shared__ float red[8];

    const float* a  = A  + (size_t)row * DD;
    const float* bp = Bv + (size_t)row * DD;

    float lsum = 0.f;
    #pragma unroll
    for (int i = 0; i < 3; i++) {
        int c = tid + i * 256;
        float v = a[c] + bp[c] + (bias ? bias[c] : 0.0f);
        buf[c] = v;
        lsum += v;
    }
    #pragma unroll
    for (int o = 16; o; o >>= 1) lsum += __shfl_xor_sync(0xffffffffu, lsum, o);
    if ((tid & 31) == 0) red[tid >> 5] = lsum;
    __syncthreads();
    float mu = (red[0]+red[1]+red[2]+red[3]+red[4]+red[5]+red[6]+red[7]) * (1.0f / DD);

    float lvar = 0.f;
    #pragma unroll
    for (int i = 0; i < 3; i++) {
        int c = tid + i * 256;
        float d = buf[c] - mu;
        lvar += d * d;
    }
    #pragma unroll
    for (int o = 16; o; o >>= 1) lvar += __shfl_xor_sync(0xffffffffu, lvar, o);
    __syncthreads();
    if ((tid & 31) == 0) red[tid >> 5] = lvar;
    __syncthreads();
    float var = (red[0]+red[1]+red[2]+red[3]+red[4]+red[5]+red[6]+red[7]) * (1.0f / DD);
    float inv = rsqrtf(var + 1e-5f);

    float* o = out + (size_t)row * DD;
    #pragma unroll
    for (int i = 0; i < 3; i++) {
        int c = tid + i * 256;
        o[c] = (buf[c] - mu) * inv * gamma[c] + beta[c];
    }
}

// ---------------------------------------------------------------------------
extern "C" void kernel_launch(void* const* d_in, const int* in_sizes, int n_in,
                              void* d_out, int out_size)
{
    const float* x   = (const float*)d_in[0];
    const float* Wq  = (const float*)d_in[2];
    const float* Wk  = (const float*)d_in[3];
    const float* Wv  = (const float*)d_in[4];
    const float* Wo  = (const float*)d_in[5];
    const float* bo  = (const float*)d_in[6];
    const float* g1  = (const float*)d_in[7];
    const float* b1  = (const float*)d_in[8];
    const float* W1  = (const float*)d_in[9];
    const float* bb1 = (const float*)d_in[10];
    const float* W2  = (const float*)d_in[11];
    const float* bb2 = (const float*)d_in[12];
    const float* g2  = (const float*)d_in[13];
    const float* b2  = (const float*)d_in[14];

    float* y = (float*)d_out;
    float* P = y + Y_ELEMS;

    float *qp, *kp, *vp, *avp, *aop, *hp, *f1p, *f2p;
    cudaGetSymbolAddress((void**)&qp,  g_q);
    cudaGetSymbolAddress((void**)&kp,  g_k);
    cudaGetSymbolAddress((void**)&vp,  g_v);
    cudaGetSymbolAddress((void**)&avp, g_av);
    cudaGetSymbolAddress((void**)&aop, g_ao);
    cudaGetSymbolAddress((void**)&hp,  g_h);
    cudaGetSymbolAddress((void**)&f1p, g_f1);
    cudaGetSymbolAddress((void**)&f2p, g_f2);

    cudaFuncSetAttribute(gemm_tc_nt, cudaFuncAttributeMaxDynamicSharedMemorySize,
                         GEMM_SMEM_BYTES);
    static const size_t att_smem = (size_t)ATT_SMEM_FLOATS * sizeof(float);
    cudaFuncSetAttribute(attn_fused, cudaFuncAttributeMaxDynamicSharedMemorySize,
                         (int)att_smem);

    dim3 g768 (DD  / 128, MM / 128);
    dim3 g3072(DFF / 128, MM / 128);

    gemm_tc_nt<<<g768, 256, GEMM_SMEM_BYTES>>>(x, Wq, qp, MM, DD, DD, 3);
    gemm_tc_nt<<<g768, 256, GEMM_SMEM_BYTES>>>(x, Wk, kp, MM, DD, DD, 3);
    gemm_tc_nt<<<g768, 256, GEMM_SMEM_BYTES>>>(x, Wv, vp, MM, DD, DD, 3);

    attn_fused<<<dim3(SS / 128, BB * HH), 512, att_smem>>>(qp, kp, vp, P, avp);

    gemm_tc_nt<<<g768, 256, GEMM_SMEM_BYTES>>>(avp, Wo, aop, MM, DD, DD, 0);

    add_ln<<<MM, 256>>>(x, aop, bo, g1, b1, hp);

    gemm_tc_nt<<<g3072, 256, GEMM_SMEM_BYTES>>>(hp, W1, f1p, MM, DFF, DD, 0);
    bias_gelu<<<(int)((size_t)MM * DFF / 4 / 256), 256>>>(f1p, bb1);
    gemm_tc_nt<<<g768, 256, GEMM_SMEM_BYTES>>>(f1p, W2, f2p, MM, DD, DFF, 0);

    add_ln<<<MM, 256>>>(hp, f2p, bb2, g2, b2, y);
}